// round 14
// baseline (speedup 1.0000x reference)
#include <cuda_runtime.h>
#include <cuda_fp16.h>
#include <cuda_bf16.h>
#include <cstdint>

#define NN      50000
#define EDGES   800000
#define ETOT    850000   // + self loops
#define BG      64
#define HID     128
#define HEADS   4
#define CH      32
#define NCLS    8
#define TSH     64
#define POOLDIM 320
#define L_LAYERS 3
#define NBLK    ((NN + 1023) / 1024)

#define NEG_INF (__int_as_float(0xff800000))

#if defined(__CUDA_ARCH_FEAT_SM103_ALL) || (defined(__CUDA_ARCH__) && defined(__CUDA_ARCH_SPECIFIC__))
#define HAS_F32X2 1
#else
#define HAS_F32X2 0
#endif

// ---------------- device scratch ----------------
__device__ float  g_h   [NN * HID];
__device__ __half g_hh_h[NN * HID];
__device__ float  g_as  [NN * HEADS];
__device__ float  g_ad  [NN * HEADS];
__device__ int    g_deg [NN];
__device__ int    g_cur [NN];
__device__ int    g_off [NN + 1];
__device__ int    g_bsum[NBLK];
__device__ int    g_csr_src[ETOT];
__device__ float  g_pool_sum[BG * HID];
__device__ float  g_pool_max[BG * HID];
__device__ float  g_cnt[BG];

__device__ __forceinline__ void atomicMaxF(float* addr, float v) {
    if (v >= 0.f) atomicMax((int*)addr, __float_as_int(v));
    else          atomicMin((unsigned int*)addr, __float_as_uint(v));
}

// ---------------- CSR build ----------------
__global__ void k_count(const int* __restrict__ ei) {
    int e = blockIdx.x * blockDim.x + threadIdx.x;
    if (e >= ETOT) return;
    int dst = (e < EDGES) ? ei[EDGES + e] : (e - EDGES);
    atomicAdd(&g_deg[dst], 1);
}
__global__ void k_scan1() {
    __shared__ int wsum[32];
    int b = blockIdx.x, tid = threadIdx.x, lane = tid & 31, wid = tid >> 5;
    int i = b * 1024 + tid;
    int v = (i < NN) ? g_deg[i] : 0;
    int x = v;
    #pragma unroll
    for (int o = 1; o < 32; o <<= 1) {
        int y = __shfl_up_sync(0xffffffffu, x, o);
        if (lane >= o) x += y;
    }
    if (lane == 31) wsum[wid] = x;
    __syncthreads();
    if (wid == 0) {
        int s = wsum[lane];
        int t = s;
        #pragma unroll
        for (int o = 1; o < 32; o <<= 1) {
            int y = __shfl_up_sync(0xffffffffu, t, o);
            if (lane >= o) t += y;
        }
        wsum[lane] = t - s;
    }
    __syncthreads();
    int incl = x + wsum[wid];
    if (i < NN) g_off[i] = incl - v;
    if (tid == 1023) g_bsum[b] = incl;
}
__global__ void k_scan2() {
    __shared__ int sh[64];
    int tid = threadIdx.x;
    int v = (tid < NBLK) ? g_bsum[tid] : 0;
    sh[tid] = v;
    __syncthreads();
    #pragma unroll
    for (int o = 1; o < 64; o <<= 1) {
        int t = (tid >= o) ? sh[tid - o] : 0;
        __syncthreads();
        sh[tid] += t;
        __syncthreads();
    }
    if (tid < NBLK) g_bsum[tid] = sh[tid] - v;
    if (tid == NBLK - 1) g_off[NN] = sh[tid];
}
__global__ void k_scan3() {
    int i = blockIdx.x * blockDim.x + threadIdx.x;
    if (i < NN) {
        int e = g_off[i] + g_bsum[i >> 10];
        g_off[i] = e;
        g_cur[i] = e;
    }
}
__global__ void k_scatter(const int* __restrict__ ei) {
    int e = blockIdx.x * blockDim.x + threadIdx.x;
    if (e >= ETOT) return;
    int src = (e < EDGES) ? ei[e]         : (e - EDGES);
    int dst = (e < EDGES) ? ei[EDGES + e] : (e - EDGES);
    int pos = atomicAdd(&g_cur[dst], 1);
    g_csr_src[pos] = src;
}

// ---------------- GEMM (f32x2) + fused attn coeffs; hh stored as fp16 ----------------
__global__ __launch_bounds__(256, 1) void k_gemm2(
        const float* __restrict__ Wl,
        const float* __restrict__ as_l, const float* __restrict__ ad_l,
        const float* __restrict__ x, const float* __restrict__ enc_w,
        const float* __restrict__ enc_b, int enc_mode) {
    extern __shared__ float smf[];
    float* sAt = smf;           // [128][128] k-major: sAt[k*128 + r]
    float* sW  = smf + 16384;   // [128][128] k-major: sW [k*128 + c]
    __shared__ float s_as[HID];
    __shared__ float s_ad[HID];
    __shared__ float s_ew[4 * HID + HID];
    int tid = threadIdx.x;
    int row0 = blockIdx.x * 128;

    if (tid < HID) { s_as[tid] = as_l[tid]; s_ad[tid] = ad_l[tid]; }

    for (int i = tid; i < 4096; i += 256)
        ((float4*)sW)[i] = ((const float4*)Wl)[i];

    if (enc_mode) {
        if (tid < 160) ((float4*)s_ew)[tid] = ((const float4*)enc_w)[tid];
        __syncthreads();
        for (int i = tid; i < 4096; i += 256) {
            int r = i & 127, q = i >> 7;
            int gr = row0 + r;
            float4 xr = (gr < NN) ? *(const float4*)(x + gr * 4)
                                  : make_float4(0.f, 0.f, 0.f, 0.f);
            #pragma unroll
            for (int j = 0; j < 4; j++) {
                int k = q * 4 + j;
                float a = s_ew[512 + k]
                        + xr.x * s_ew[k] + xr.y * s_ew[128 + k]
                        + xr.z * s_ew[256 + k] + xr.w * s_ew[384 + k];
                sAt[k * 128 + r] = (gr < NN) ? fmaxf(a, 0.f) : 0.f;
            }
        }
    } else {
        for (int i = tid; i < 4096; i += 256) {
            int r = i & 127, q = i >> 7;
            int gr = row0 + r;
            float4 v = (gr < NN) ? *(const float4*)(g_h + gr * 128 + q * 4)
                                 : make_float4(0.f, 0.f, 0.f, 0.f);
            sAt[(q * 4 + 0) * 128 + r] = v.x;
            sAt[(q * 4 + 1) * 128 + r] = v.y;
            sAt[(q * 4 + 2) * 128 + r] = v.z;
            sAt[(q * 4 + 3) * 128 + r] = v.w;
        }
    }
    __syncthreads();

    int ty = tid >> 4, tx = tid & 15;

#if HAS_F32X2
    unsigned long long acc[8][4];
    #pragma unroll
    for (int i = 0; i < 8; i++)
        #pragma unroll
        for (int j = 0; j < 4; j++) acc[i][j] = 0ull;

    #pragma unroll 2
    for (int k = 0; k < 128; k++) {
        const float* ak = sAt + k * 128 + ty * 8;
        float4 a0 = *(const float4*)ak;
        float4 a1 = *(const float4*)(ak + 4);
        const float* wk = sW + k * 128 + tx * 8;
        float4 w0 = *(const float4*)wk;
        float4 w1 = *(const float4*)(wk + 4);
        unsigned long long wp[4];
        asm("mov.b64 %0, {%1, %2};" : "=l"(wp[0]) : "f"(w0.x), "f"(w0.y));
        asm("mov.b64 %0, {%1, %2};" : "=l"(wp[1]) : "f"(w0.z), "f"(w0.w));
        asm("mov.b64 %0, {%1, %2};" : "=l"(wp[2]) : "f"(w1.x), "f"(w1.y));
        asm("mov.b64 %0, {%1, %2};" : "=l"(wp[3]) : "f"(w1.z), "f"(w1.w));
        float av[8] = {a0.x, a0.y, a0.z, a0.w, a1.x, a1.y, a1.z, a1.w};
        #pragma unroll
        for (int i = 0; i < 8; i++) {
            unsigned long long a2;
            asm("mov.b64 %0, {%1, %1};" : "=l"(a2) : "f"(av[i]));
            #pragma unroll
            for (int j = 0; j < 4; j++)
                asm("fma.rn.f32x2 %0, %1, %2, %0;"
                    : "+l"(acc[i][j]) : "l"(a2), "l"(wp[j]));
        }
    }

    #pragma unroll
    for (int i = 0; i < 8; i++) {
        int row = row0 + ty * 8 + i;
        float c[8];
        #pragma unroll
        for (int j = 0; j < 4; j++)
            asm("mov.b64 {%0, %1}, %2;" : "=f"(c[2*j]), "=f"(c[2*j+1]) : "l"(acc[i][j]));
        float ps = 0.f, pd = 0.f;
        #pragma unroll
        for (int j = 0; j < 8; j++) {
            ps += c[j] * s_as[tx * 8 + j];
            pd += c[j] * s_ad[tx * 8 + j];
        }
        ps += __shfl_xor_sync(0xffffffffu, ps, 1, 4);
        ps += __shfl_xor_sync(0xffffffffu, ps, 2, 4);
        pd += __shfl_xor_sync(0xffffffffu, pd, 1, 4);
        pd += __shfl_xor_sync(0xffffffffu, pd, 2, 4);
        if (row < NN) {
            __half hb[8];
            #pragma unroll
            for (int j = 0; j < 8; j++) hb[j] = __float2half_rn(c[j]);
            *(uint4*)(g_hh_h + row * 128 + tx * 8) = *(const uint4*)hb;
            if ((tx & 3) == 0) {
                g_as[row * 4 + (tx >> 2)] = ps;
                g_ad[row * 4 + (tx >> 2)] = pd;
            }
        }
    }
#else
    float acc[8][8];
    #pragma unroll
    for (int i = 0; i < 8; i++)
        #pragma unroll
        for (int j = 0; j < 8; j++) acc[i][j] = 0.f;

    #pragma unroll 2
    for (int k = 0; k < 128; k++) {
        const float* ak = sAt + k * 128 + ty * 8;
        float4 a0 = *(const float4*)ak;
        float4 a1 = *(const float4*)(ak + 4);
        const float* wk = sW + k * 128 + tx * 8;
        float4 w0 = *(const float4*)wk;
        float4 w1 = *(const float4*)(wk + 4);
        float av[8] = {a0.x, a0.y, a0.z, a0.w, a1.x, a1.y, a1.z, a1.w};
        float wv[8] = {w0.x, w0.y, w0.z, w0.w, w1.x, w1.y, w1.z, w1.w};
        #pragma unroll
        for (int i = 0; i < 8; i++)
            #pragma unroll
            for (int j = 0; j < 8; j++) acc[i][j] += av[i] * wv[j];
    }

    #pragma unroll
    for (int i = 0; i < 8; i++) {
        int row = row0 + ty * 8 + i;
        float ps = 0.f, pd = 0.f;
        #pragma unroll
        for (int j = 0; j < 8; j++) {
            ps += acc[i][j] * s_as[tx * 8 + j];
            pd += acc[i][j] * s_ad[tx * 8 + j];
        }
        ps += __shfl_xor_sync(0xffffffffu, ps, 1, 4);
        ps += __shfl_xor_sync(0xffffffffu, ps, 2, 4);
        pd += __shfl_xor_sync(0xffffffffu, pd, 1, 4);
        pd += __shfl_xor_sync(0xffffffffu, pd, 2, 4);
        if (row < NN) {
            __half hb[8];
            #pragma unroll
            for (int j = 0; j < 8; j++) hb[j] = __float2half_rn(acc[i][j]);
            *(uint4*)(g_hh_h + row * 128 + tx * 8) = *(const uint4*)hb;
            if ((tx & 3) == 0) {
                g_as[row * 4 + (tx >> 2)] = ps;
                g_ad[row * 4 + (tx >> 2)] = pd;
            }
        }
    }
#endif
}

// ---------------- GAT aggregation: warp/node (frozen R8 shape), no-max softmax ----------------
__global__ void k_agg(const float* __restrict__ bias) {
    int w = threadIdx.x >> 5, lane = threadIdx.x & 31;
    int n = blockIdx.x * 8 + w;
    __shared__ int   s_src[8][32];
    __shared__ float s_wv[8][128];
    if (n >= NN) return;

    int beg = g_off[n], end = g_off[n + 1];
    int deg = end - beg;
    float4 ad4 = *(const float4*)(g_ad + n * 4);
    int hd = lane >> 3;
    const __half* hhp = g_hh_h + lane * 4;

    float acc0 = 0.f, acc1 = 0.f, acc2 = 0.f, acc3 = 0.f;
    float sw0 = 0.f, sw1 = 0.f, sw2 = 0.f, sw3 = 0.f;

    if (deg <= 32) {
        int i = beg + lane;
        bool ok = i < end;
        int sidx = ok ? g_csr_src[i] : 0;
        float w0 = 0.f, w1 = 0.f, w2 = 0.f, w3 = 0.f;
        if (ok) {
            float4 a4 = *(const float4*)(g_as + sidx * 4);
            float v;
            v = a4.x + ad4.x; v = v > 0.f ? v : 0.2f * v; w0 = __expf(v);
            v = a4.y + ad4.y; v = v > 0.f ? v : 0.2f * v; w1 = __expf(v);
            v = a4.z + ad4.z; v = v > 0.f ? v : 0.2f * v; w2 = __expf(v);
            v = a4.w + ad4.w; v = v > 0.f ? v : 0.2f * v; w3 = __expf(v);
        }
        sw0 = w0; sw1 = w1; sw2 = w2; sw3 = w3;
        s_src[w][lane] = sidx;
        *(float4*)&s_wv[w][lane * 4] = make_float4(w0, w1, w2, w3);
        __syncwarp();

        int nbp = (deg + 3) & ~3;
        for (int j0 = 0; j0 < nbp; j0 += 4) {
            int srcs[4]; float wj[4]; uint2 u[4];
            #pragma unroll
            for (int j = 0; j < 4; j++) srcs[j] = s_src[w][j0 + j];
            #pragma unroll
            for (int j = 0; j < 4; j++) wj[j] = s_wv[w][(j0 + j) * 4 + hd];
            #pragma unroll
            for (int j = 0; j < 4; j++) u[j] = *(const uint2*)(hhp + srcs[j] * 128);
            #pragma unroll
            for (int j = 0; j < 4; j++) {
                float2 f0 = __half22float2(*(const __half2*)&u[j].x);
                float2 f1 = __half22float2(*(const __half2*)&u[j].y);
                acc0 += wj[j] * f0.x;
                acc1 += wj[j] * f0.y;
                acc2 += wj[j] * f1.x;
                acc3 += wj[j] * f1.y;
            }
        }
    } else {
        for (int base = beg; base < end; base += 32) {
            int i = base + lane;
            float w0 = 0.f, w1 = 0.f, w2 = 0.f, w3 = 0.f;
            int sidx = 0;
            if (i < end) {
                sidx = g_csr_src[i];
                float4 a4 = *(const float4*)(g_as + sidx * 4);
                float v;
                v = a4.x + ad4.x; v = v > 0.f ? v : 0.2f * v; w0 = __expf(v);
                v = a4.y + ad4.y; v = v > 0.f ? v : 0.2f * v; w1 = __expf(v);
                v = a4.z + ad4.z; v = v > 0.f ? v : 0.2f * v; w2 = __expf(v);
                v = a4.w + ad4.w; v = v > 0.f ? v : 0.2f * v; w3 = __expf(v);
            }
            sw0 += w0; sw1 += w1; sw2 += w2; sw3 += w3;
            s_src[w][lane] = sidx;
            *(float4*)&s_wv[w][lane * 4] = make_float4(w0, w1, w2, w3);
            __syncwarp();
            int nb = min(32, end - base);
            int nbp = (nb + 3) & ~3;
            for (int j0 = 0; j0 < nbp; j0 += 4) {
                int srcs[4]; float wj[4]; uint2 u[4];
                #pragma unroll
                for (int j = 0; j < 4; j++) srcs[j] = s_src[w][j0 + j];
                #pragma unroll
                for (int j = 0; j < 4; j++) wj[j] = s_wv[w][(j0 + j) * 4 + hd];
                #pragma unroll
                for (int j = 0; j < 4; j++) u[j] = *(const uint2*)(hhp + srcs[j] * 128);
                #pragma unroll
                for (int j = 0; j < 4; j++) {
                    float2 f0 = __half22float2(*(const __half2*)&u[j].x);
                    float2 f1 = __half22float2(*(const __half2*)&u[j].y);
                    acc0 += wj[j] * f0.x;
                    acc1 += wj[j] * f0.y;
                    acc2 += wj[j] * f1.x;
                    acc3 += wj[j] * f1.y;
                }
            }
            __syncwarp();
        }
    }

    #pragma unroll
    for (int o = 16; o > 0; o >>= 1) {
        sw0 += __shfl_xor_sync(0xffffffffu, sw0, o);
        sw1 += __shfl_xor_sync(0xffffffffu, sw1, o);
        sw2 += __shfl_xor_sync(0xffffffffu, sw2, o);
        sw3 += __shfl_xor_sync(0xffffffffu, sw3, o);
    }
    float denom = (hd == 0) ? sw0 : (hd == 1) ? sw1 : (hd == 2) ? sw2 : sw3;
    float inv = 1.f / denom;
    float4 b4 = *(const float4*)(bias + lane * 4);
    float4 o4;
    o4.x = fmaxf(acc0 * inv + b4.x, 0.f);
    o4.y = fmaxf(acc1 * inv + b4.y, 0.f);
    o4.z = fmaxf(acc2 * inv + b4.z, 0.f);
    o4.w = fmaxf(acc3 * inv + b4.w, 0.f);
    *(float4*)(g_h + n * 128 + lane * 4) = o4;
}

// ---------------- pooling ----------------
__global__ void k_pool_init() {
    int i = blockIdx.x * blockDim.x + threadIdx.x;
    if (i < BG * HID) { g_pool_sum[i] = 0.f; g_pool_max[i] = NEG_INF; }
    if (i < BG) g_cnt[i] = 0.f;
}
__global__ void k_pool(const int* __restrict__ batch) {
    const int NPB = 128;
    int c = threadIdx.x;
    int n0 = blockIdx.x * NPB;
    int n1 = min(n0 + NPB, NN);
    float sum = 0.f, mx = NEG_INF;
    int curb = batch[n0];
    int runlen = 0;
    for (int n = n0; n < n1; n++) {
        int b = batch[n];
        if (b != curb) {
            atomicAdd(&g_pool_sum[curb * HID + c], sum);
            atomicMaxF(&g_pool_max[curb * HID + c], mx);
            if (c == 0) atomicAdd(&g_cnt[curb], (float)runlen);
            sum = 0.f; mx = NEG_INF; runlen = 0; curb = b;
        }
        float v = g_h[n * HID + c];
        sum += v; mx = fmaxf(mx, v); runlen++;
    }
    atomicAdd(&g_pool_sum[curb * HID + c], sum);
    atomicMaxF(&g_pool_max[curb * HID + c], mx);
    if (c == 0) atomicAdd(&g_cnt[curb], (float)runlen);
}

// ---------------- fused head ----------------
__device__ __forceinline__ float blk_reduce_sum320(float v, float* sc) {
    int lane = threadIdx.x & 31, wid = threadIdx.x >> 5;
    #pragma unroll
    for (int o = 16; o > 0; o >>= 1) v += __shfl_xor_sync(0xffffffffu, v, o);
    if (lane == 0) sc[wid] = v;
    __syncthreads();
    float r = 0.f;
    if (wid == 0) {
        r = (lane < 10) ? sc[lane] : 0.f;
        #pragma unroll
        for (int o = 16; o > 0; o >>= 1) r += __shfl_xor_sync(0xffffffffu, r, o);
        if (lane == 0) sc[0] = r;
    }
    __syncthreads();
    r = sc[0];
    __syncthreads();
    return r;
}
__global__ void k_head(float* __restrict__ out, const float* __restrict__ ts,
                       const float* __restrict__ tw1, const float* __restrict__ tb1,
                       const float* __restrict__ tg,  const float* __restrict__ tbln,
                       const float* __restrict__ tw2, const float* __restrict__ tb2,
                       const float* __restrict__ cg,  const float* __restrict__ cbln,
                       const float* __restrict__ cw1, const float* __restrict__ cb1,
                       const float* __restrict__ cw2, const float* __restrict__ cb2) {
    int b = blockIdx.x, t = threadIdx.x;
    int lane = t & 31;
    __shared__ float z[POOLDIM];
    __shared__ float y[HID];
    __shared__ float sc[16];
    __shared__ float tsh[64];
    __shared__ float tws[2];

    float t1 = 0.f;
    bool is_ts = (t >= 256);
    int j = t - 256;
    if (is_ts)
        t1 = tb1[j] + ts[b * 3 + 0] * tw1[j] + ts[b * 3 + 1] * tw1[64 + j]
                    + ts[b * 3 + 2] * tw1[128 + j];
    float r = is_ts ? t1 : 0.f;
    #pragma unroll
    for (int o = 16; o > 0; o >>= 1) r += __shfl_xor_sync(0xffffffffu, r, o);
    if (is_ts && lane == 0) tws[j >> 5] = r;
    __syncthreads();
    float mean64 = (tws[0] + tws[1]) * (1.f / 64.f);
    __syncthreads();
    float dd = is_ts ? (t1 - mean64) : 0.f;
    r = dd * dd;
    #pragma unroll
    for (int o = 16; o > 0; o >>= 1) r += __shfl_xor_sync(0xffffffffu, r, o);
    if (is_ts && lane == 0) tws[j >> 5] = r;
    __syncthreads();
    float var64 = (tws[0] + tws[1]) * (1.f / 64.f);
    if (is_ts)
        tsh[j] = fmaxf(dd * rsqrtf(var64 + 1e-5f) * tg[j] + tbln[j], 0.f);
    __syncthreads();

    float v;
    if (is_ts) {
        float o2 = tb2[j];
        #pragma unroll 8
        for (int k = 0; k < 64; k++) o2 += tsh[k] * tw2[k * 64 + j];
        v = o2;
    } else if (t < 128) {
        v = g_pool_sum[b * HID + t] / fmaxf(g_cnt[b], 1.f);
    } else {
        v = g_pool_max[b * HID + (t - 128)];
    }

    float mean = blk_reduce_sum320(v, sc) * (1.f / (float)POOLDIM);
    float d = v - mean;
    float var = blk_reduce_sum320(d * d, sc) * (1.f / (float)POOLDIM);
    z[t] = d * rsqrtf(var + 1e-5f) * cg[t] + cbln[t];
    __syncthreads();

    if (t < HID) {
        float a = cb1[t];
        #pragma unroll 8
        for (int k = 0; k < POOLDIM; k++) a += z[k] * cw1[k * HID + t];
        y[t] = fmaxf(a, 0.f);
    }
    __syncthreads();
    if (t < NCLS) {
        float a = cb2[t];
        #pragma unroll 8
        for (int k = 0; k < HID; k++) a += y[k] * cw2[k * NCLS + t];
        out[b * NCLS + t] = a;
    }
}

// ---------------- launch ----------------
extern "C" void kernel_launch(void* const* d_in, const int* in_sizes, int n_in,
                              void* d_out, int out_size) {
    const float* x      = (const float*)d_in[0];
    const int*   ei     = (const int*)  d_in[1];
    const int*   batch  = (const int*)  d_in[2];
    const float* ts     = (const float*)d_in[3];
    const float* enc_w  = (const float*)d_in[4];
    const float* enc_b  = (const float*)d_in[5];
    const float* gat_w  = (const float*)d_in[6];
    const float* gat_as = (const float*)d_in[7];
    const float* gat_ad = (const float*)d_in[8];
    const float* gat_b  = (const float*)d_in[9];
    const float* ts_w1  = (const float*)d_in[10];
    const float* ts_b1  = (const float*)d_in[11];
    const float* ts_g   = (const float*)d_in[12];
    const float* ts_bln = (const float*)d_in[13];
    const float* ts_w2  = (const float*)d_in[14];
    const float* ts_b2  = (const float*)d_in[15];
    const float* cls_g  = (const float*)d_in[16];
    const float* cls_bln= (const float*)d_in[17];
    const float* cls_w1 = (const float*)d_in[18];
    const float* cls_b1 = (const float*)d_in[19];
    const float* cls_w2 = (const float*)d_in[20];
    const float* cls_b2 = (const float*)d_in[21];
    float* out = (float*)d_out;

    const int GEMM_SMEM = 131072;
    static bool init_done = false;
    static bool have_s2 = false;
    static cudaStream_t s2 = nullptr;
    static cudaEvent_t evF = nullptr, evJ = nullptr;
    static void* deg_addr = nullptr;
    if (!init_done) {
        cudaFuncSetAttribute(k_gemm2, cudaFuncAttributeMaxDynamicSharedMemorySize, GEMM_SMEM);
        cudaGetSymbolAddress(&deg_addr, g_deg);
        if (cudaStreamCreateWithFlags(&s2, cudaStreamNonBlocking) == cudaSuccess &&
            cudaEventCreateWithFlags(&evF, cudaEventDisableTiming) == cudaSuccess &&
            cudaEventCreateWithFlags(&evJ, cudaEventDisableTiming) == cudaSuccess) {
            have_s2 = true;
        }
        init_done = true;
    }

    cudaStream_t sc = have_s2 ? s2 : (cudaStream_t)0;

    // fork: CSR build on side stream (or serial on stream 0 if fork unavailable)
    if (have_s2) {
        cudaEventRecord(evF, 0);
        cudaStreamWaitEvent(s2, evF, 0);
    }
    cudaMemsetAsync(deg_addr, 0, NN * sizeof(int), sc);
    k_count  <<<(ETOT + 255) / 256, 256, 0, sc>>>(ei);
    k_scan1  <<<NBLK, 1024, 0, sc>>>();
    k_scan2  <<<1, 64, 0, sc>>>();
    k_scan3  <<<(NN + 255) / 256, 256, 0, sc>>>();
    k_scatter<<<(ETOT + 255) / 256, 256, 0, sc>>>(ei);
    k_pool_init<<<(BG * HID + 255) / 256, 256, 0, sc>>>();
    if (have_s2) cudaEventRecord(evJ, s2);

    // main stream: layer-0 GEMM with fused encoder (runs concurrent with CSR build)
    k_gemm2<<<(NN + 127) / 128, 256, GEMM_SMEM>>>(
        gat_w, gat_as, gat_ad, x, enc_w, enc_b, 1);

    if (have_s2) cudaStreamWaitEvent(0, evJ, 0);

    k_agg<<<(NN + 7) / 8, 256>>>(gat_b);
    for (int l = 1; l < 3; l++) {
        k_gemm2<<<(NN + 127) / 128, 256, GEMM_SMEM>>>(
            gat_w + l * HID * HID,
            gat_as + l * HEADS * CH, gat_ad + l * HEADS * CH,
            nullptr, nullptr, nullptr, 0);
        k_agg<<<(NN + 7) / 8, 256>>>(gat_b + l * HID);
    }

    k_pool<<<(NN + 127) / 128, 128>>>(batch);
    k_head<<<BG, POOLDIM>>>(out, ts,
                            ts_w1, ts_b1, ts_g, ts_bln, ts_w2, ts_b2,
                            cls_g, cls_bln, cls_w1, cls_b1, cls_w2, cls_b2);
}

// round 15
// speedup vs baseline: 1.0081x; 1.0081x over previous
#include <cuda_runtime.h>
#include <cuda_fp16.h>
#include <cuda_bf16.h>
#include <cstdint>

#define NN      50000
#define EDGES   800000
#define ETOT    850000   // + self loops
#define BG      64
#define HID     128
#define HEADS   4
#define CH      32
#define NCLS    8
#define TSH     64
#define POOLDIM 320
#define L_LAYERS 3
#define NBLK    ((NN + 1023) / 1024)

#define NEG_INF (__int_as_float(0xff800000))

#if defined(__CUDA_ARCH_FEAT_SM103_ALL) || (defined(__CUDA_ARCH__) && defined(__CUDA_ARCH_SPECIFIC__))
#define HAS_F32X2 1
#else
#define HAS_F32X2 0
#endif

// ---------------- device scratch ----------------
__device__ float  g_h   [NN * HID];
__device__ __half g_hh_h[NN * HID];
__device__ float  g_as  [NN * HEADS];
__device__ float  g_ad  [NN * HEADS];
__device__ int    g_deg [NN];
__device__ int    g_cur [NN];
__device__ int    g_off [NN + 1];
__device__ int    g_bsum[NBLK];
__device__ int    g_csr_src[ETOT];
__device__ float  g_pool_sum[BG * HID];
__device__ float  g_pool_max[BG * HID];
__device__ float  g_cnt[BG];

__device__ __forceinline__ void atomicMaxF(float* addr, float v) {
    if (v >= 0.f) atomicMax((int*)addr, __float_as_int(v));
    else          atomicMin((unsigned int*)addr, __float_as_uint(v));
}

// ---------------- CSR build ----------------
__global__ void k_zero_deg() {
    int i = blockIdx.x * blockDim.x + threadIdx.x;
    if (i < NN) g_deg[i] = 0;
}
__global__ void k_count(const int* __restrict__ ei) {
    int e = blockIdx.x * blockDim.x + threadIdx.x;
    if (e >= ETOT) return;
    int dst = (e < EDGES) ? ei[EDGES + e] : (e - EDGES);
    atomicAdd(&g_deg[dst], 1);
}
__global__ void k_scan1() {
    __shared__ int wsum[32];
    int b = blockIdx.x, tid = threadIdx.x, lane = tid & 31, wid = tid >> 5;
    int i = b * 1024 + tid;
    int v = (i < NN) ? g_deg[i] : 0;
    int x = v;
    #pragma unroll
    for (int o = 1; o < 32; o <<= 1) {
        int y = __shfl_up_sync(0xffffffffu, x, o);
        if (lane >= o) x += y;
    }
    if (lane == 31) wsum[wid] = x;
    __syncthreads();
    if (wid == 0) {
        int s = wsum[lane];
        int t = s;
        #pragma unroll
        for (int o = 1; o < 32; o <<= 1) {
            int y = __shfl_up_sync(0xffffffffu, t, o);
            if (lane >= o) t += y;
        }
        wsum[lane] = t - s;
    }
    __syncthreads();
    int incl = x + wsum[wid];
    if (i < NN) g_off[i] = incl - v;
    if (tid == 1023) g_bsum[b] = incl;
}
__global__ void k_scan2() {
    __shared__ int sh[64];
    int tid = threadIdx.x;
    int v = (tid < NBLK) ? g_bsum[tid] : 0;
    sh[tid] = v;
    __syncthreads();
    #pragma unroll
    for (int o = 1; o < 64; o <<= 1) {
        int t = (tid >= o) ? sh[tid - o] : 0;
        __syncthreads();
        sh[tid] += t;
        __syncthreads();
    }
    if (tid < NBLK) g_bsum[tid] = sh[tid] - v;
    if (tid == NBLK - 1) g_off[NN] = sh[tid];
}
__global__ void k_scan3() {
    int i = blockIdx.x * blockDim.x + threadIdx.x;
    if (i < NN) {
        int e = g_off[i] + g_bsum[i >> 10];
        g_off[i] = e;
        g_cur[i] = e;
    }
}
__global__ void k_scatter(const int* __restrict__ ei) {
    int e = blockIdx.x * blockDim.x + threadIdx.x;
    if (e >= ETOT) return;
    int src = (e < EDGES) ? ei[e]         : (e - EDGES);
    int dst = (e < EDGES) ? ei[EDGES + e] : (e - EDGES);
    int pos = atomicAdd(&g_cur[dst], 1);
    g_csr_src[pos] = src;
}

// ---------------- GEMM (f32x2) + fused attn coeffs; hh stored as fp16 ----------------
__global__ __launch_bounds__(256, 1) void k_gemm2(
        const float* __restrict__ Wl,
        const float* __restrict__ as_l, const float* __restrict__ ad_l,
        const float* __restrict__ x, const float* __restrict__ enc_w,
        const float* __restrict__ enc_b, int enc_mode) {
    extern __shared__ float smf[];
    float* sAt = smf;           // [128][128] k-major: sAt[k*128 + r]
    float* sW  = smf + 16384;   // [128][128] k-major: sW [k*128 + c]
    __shared__ float s_as[HID];
    __shared__ float s_ad[HID];
    __shared__ float s_ew[4 * HID + HID];
    int tid = threadIdx.x;
    int row0 = blockIdx.x * 128;

    if (tid < HID) { s_as[tid] = as_l[tid]; s_ad[tid] = ad_l[tid]; }

    for (int i = tid; i < 4096; i += 256)
        ((float4*)sW)[i] = ((const float4*)Wl)[i];

    if (enc_mode) {
        if (tid < 160) ((float4*)s_ew)[tid] = ((const float4*)enc_w)[tid];
        __syncthreads();
        for (int i = tid; i < 4096; i += 256) {
            int r = i & 127, q = i >> 7;
            int gr = row0 + r;
            float4 xr = (gr < NN) ? *(const float4*)(x + gr * 4)
                                  : make_float4(0.f, 0.f, 0.f, 0.f);
            #pragma unroll
            for (int j = 0; j < 4; j++) {
                int k = q * 4 + j;
                float a = s_ew[512 + k]
                        + xr.x * s_ew[k] + xr.y * s_ew[128 + k]
                        + xr.z * s_ew[256 + k] + xr.w * s_ew[384 + k];
                sAt[k * 128 + r] = (gr < NN) ? fmaxf(a, 0.f) : 0.f;
            }
        }
    } else {
        for (int i = tid; i < 4096; i += 256) {
            int r = i & 127, q = i >> 7;
            int gr = row0 + r;
            float4 v = (gr < NN) ? *(const float4*)(g_h + gr * 128 + q * 4)
                                 : make_float4(0.f, 0.f, 0.f, 0.f);
            sAt[(q * 4 + 0) * 128 + r] = v.x;
            sAt[(q * 4 + 1) * 128 + r] = v.y;
            sAt[(q * 4 + 2) * 128 + r] = v.z;
            sAt[(q * 4 + 3) * 128 + r] = v.w;
        }
    }
    __syncthreads();

    int ty = tid >> 4, tx = tid & 15;

#if HAS_F32X2
    unsigned long long acc[8][4];
    #pragma unroll
    for (int i = 0; i < 8; i++)
        #pragma unroll
        for (int j = 0; j < 4; j++) acc[i][j] = 0ull;

    #pragma unroll 2
    for (int k = 0; k < 128; k++) {
        const float* ak = sAt + k * 128 + ty * 8;
        float4 a0 = *(const float4*)ak;
        float4 a1 = *(const float4*)(ak + 4);
        const float* wk = sW + k * 128 + tx * 8;
        float4 w0 = *(const float4*)wk;
        float4 w1 = *(const float4*)(wk + 4);
        unsigned long long wp[4];
        asm("mov.b64 %0, {%1, %2};" : "=l"(wp[0]) : "f"(w0.x), "f"(w0.y));
        asm("mov.b64 %0, {%1, %2};" : "=l"(wp[1]) : "f"(w0.z), "f"(w0.w));
        asm("mov.b64 %0, {%1, %2};" : "=l"(wp[2]) : "f"(w1.x), "f"(w1.y));
        asm("mov.b64 %0, {%1, %2};" : "=l"(wp[3]) : "f"(w1.z), "f"(w1.w));
        float av[8] = {a0.x, a0.y, a0.z, a0.w, a1.x, a1.y, a1.z, a1.w};
        #pragma unroll
        for (int i = 0; i < 8; i++) {
            unsigned long long a2;
            asm("mov.b64 %0, {%1, %1};" : "=l"(a2) : "f"(av[i]));
            #pragma unroll
            for (int j = 0; j < 4; j++)
                asm("fma.rn.f32x2 %0, %1, %2, %0;"
                    : "+l"(acc[i][j]) : "l"(a2), "l"(wp[j]));
        }
    }

    #pragma unroll
    for (int i = 0; i < 8; i++) {
        int row = row0 + ty * 8 + i;
        float c[8];
        #pragma unroll
        for (int j = 0; j < 4; j++)
            asm("mov.b64 {%0, %1}, %2;" : "=f"(c[2*j]), "=f"(c[2*j+1]) : "l"(acc[i][j]));
        float ps = 0.f, pd = 0.f;
        #pragma unroll
        for (int j = 0; j < 8; j++) {
            ps += c[j] * s_as[tx * 8 + j];
            pd += c[j] * s_ad[tx * 8 + j];
        }
        ps += __shfl_xor_sync(0xffffffffu, ps, 1, 4);
        ps += __shfl_xor_sync(0xffffffffu, ps, 2, 4);
        pd += __shfl_xor_sync(0xffffffffu, pd, 1, 4);
        pd += __shfl_xor_sync(0xffffffffu, pd, 2, 4);
        if (row < NN) {
            __half hb[8];
            #pragma unroll
            for (int j = 0; j < 8; j++) hb[j] = __float2half_rn(c[j]);
            *(uint4*)(g_hh_h + row * 128 + tx * 8) = *(const uint4*)hb;
            if ((tx & 3) == 0) {
                g_as[row * 4 + (tx >> 2)] = ps;
                g_ad[row * 4 + (tx >> 2)] = pd;
            }
        }
    }
#else
    float acc[8][8];
    #pragma unroll
    for (int i = 0; i < 8; i++)
        #pragma unroll
        for (int j = 0; j < 8; j++) acc[i][j] = 0.f;

    #pragma unroll 2
    for (int k = 0; k < 128; k++) {
        const float* ak = sAt + k * 128 + ty * 8;
        float4 a0 = *(const float4*)ak;
        float4 a1 = *(const float4*)(ak + 4);
        const float* wk = sW + k * 128 + tx * 8;
        float4 w0 = *(const float4*)wk;
        float4 w1 = *(const float4*)(wk + 4);
        float av[8] = {a0.x, a0.y, a0.z, a0.w, a1.x, a1.y, a1.z, a1.w};
        float wv[8] = {w0.x, w0.y, w0.z, w0.w, w1.x, w1.y, w1.z, w1.w};
        #pragma unroll
        for (int i = 0; i < 8; i++)
            #pragma unroll
            for (int j = 0; j < 8; j++) acc[i][j] += av[i] * wv[j];
    }

    #pragma unroll
    for (int i = 0; i < 8; i++) {
        int row = row0 + ty * 8 + i;
        float ps = 0.f, pd = 0.f;
        #pragma unroll
        for (int j = 0; j < 8; j++) {
            ps += acc[i][j] * s_as[tx * 8 + j];
            pd += acc[i][j] * s_ad[tx * 8 + j];
        }
        ps += __shfl_xor_sync(0xffffffffu, ps, 1, 4);
        ps += __shfl_xor_sync(0xffffffffu, ps, 2, 4);
        pd += __shfl_xor_sync(0xffffffffu, pd, 1, 4);
        pd += __shfl_xor_sync(0xffffffffu, pd, 2, 4);
        if (row < NN) {
            __half hb[8];
            #pragma unroll
            for (int j = 0; j < 8; j++) hb[j] = __float2half_rn(acc[i][j]);
            *(uint4*)(g_hh_h + row * 128 + tx * 8) = *(const uint4*)hb;
            if ((tx & 3) == 0) {
                g_as[row * 4 + (tx >> 2)] = ps;
                g_ad[row * 4 + (tx >> 2)] = pd;
            }
        }
    }
#endif
}

// ---------------- GAT aggregation: warp/node (frozen R8 shape), no-max softmax ----------------
__global__ void k_agg(const float* __restrict__ bias) {
    int w = threadIdx.x >> 5, lane = threadIdx.x & 31;
    int n = blockIdx.x * 8 + w;
    __shared__ int   s_src[8][32];
    __shared__ float s_wv[8][128];
    if (n >= NN) return;

    int beg = g_off[n], end = g_off[n + 1];
    int deg = end - beg;
    float4 ad4 = *(const float4*)(g_ad + n * 4);
    int hd = lane >> 3;
    const __half* hhp = g_hh_h + lane * 4;

    float acc0 = 0.f, acc1 = 0.f, acc2 = 0.f, acc3 = 0.f;
    float sw0 = 0.f, sw1 = 0.f, sw2 = 0.f, sw3 = 0.f;

    if (deg <= 32) {
        int i = beg + lane;
        bool ok = i < end;
        int sidx = ok ? g_csr_src[i] : 0;
        float w0 = 0.f, w1 = 0.f, w2 = 0.f, w3 = 0.f;
        if (ok) {
            float4 a4 = *(const float4*)(g_as + sidx * 4);
            float v;
            v = a4.x + ad4.x; v = v > 0.f ? v : 0.2f * v; w0 = __expf(v);
            v = a4.y + ad4.y; v = v > 0.f ? v : 0.2f * v; w1 = __expf(v);
            v = a4.z + ad4.z; v = v > 0.f ? v : 0.2f * v; w2 = __expf(v);
            v = a4.w + ad4.w; v = v > 0.f ? v : 0.2f * v; w3 = __expf(v);
        }
        sw0 = w0; sw1 = w1; sw2 = w2; sw3 = w3;
        s_src[w][lane] = sidx;
        *(float4*)&s_wv[w][lane * 4] = make_float4(w0, w1, w2, w3);
        __syncwarp();

        int nbp = (deg + 3) & ~3;
        for (int j0 = 0; j0 < nbp; j0 += 4) {
            int srcs[4]; float wj[4]; uint2 u[4];
            #pragma unroll
            for (int j = 0; j < 4; j++) srcs[j] = s_src[w][j0 + j];
            #pragma unroll
            for (int j = 0; j < 4; j++) wj[j] = s_wv[w][(j0 + j) * 4 + hd];
            #pragma unroll
            for (int j = 0; j < 4; j++) u[j] = *(const uint2*)(hhp + srcs[j] * 128);
            #pragma unroll
            for (int j = 0; j < 4; j++) {
                float2 f0 = __half22float2(*(const __half2*)&u[j].x);
                float2 f1 = __half22float2(*(const __half2*)&u[j].y);
                acc0 += wj[j] * f0.x;
                acc1 += wj[j] * f0.y;
                acc2 += wj[j] * f1.x;
                acc3 += wj[j] * f1.y;
            }
        }
    } else {
        for (int base = beg; base < end; base += 32) {
            int i = base + lane;
            float w0 = 0.f, w1 = 0.f, w2 = 0.f, w3 = 0.f;
            int sidx = 0;
            if (i < end) {
                sidx = g_csr_src[i];
                float4 a4 = *(const float4*)(g_as + sidx * 4);
                float v;
                v = a4.x + ad4.x; v = v > 0.f ? v : 0.2f * v; w0 = __expf(v);
                v = a4.y + ad4.y; v = v > 0.f ? v : 0.2f * v; w1 = __expf(v);
                v = a4.z + ad4.z; v = v > 0.f ? v : 0.2f * v; w2 = __expf(v);
                v = a4.w + ad4.w; v = v > 0.f ? v : 0.2f * v; w3 = __expf(v);
            }
            sw0 += w0; sw1 += w1; sw2 += w2; sw3 += w3;
            s_src[w][lane] = sidx;
            *(float4*)&s_wv[w][lane * 4] = make_float4(w0, w1, w2, w3);
            __syncwarp();
            int nb = min(32, end - base);
            int nbp = (nb + 3) & ~3;
            for (int j0 = 0; j0 < nbp; j0 += 4) {
                int srcs[4]; float wj[4]; uint2 u[4];
                #pragma unroll
                for (int j = 0; j < 4; j++) srcs[j] = s_src[w][j0 + j];
                #pragma unroll
                for (int j = 0; j < 4; j++) wj[j] = s_wv[w][(j0 + j) * 4 + hd];
                #pragma unroll
                for (int j = 0; j < 4; j++) u[j] = *(const uint2*)(hhp + srcs[j] * 128);
                #pragma unroll
                for (int j = 0; j < 4; j++) {
                    float2 f0 = __half22float2(*(const __half2*)&u[j].x);
                    float2 f1 = __half22float2(*(const __half2*)&u[j].y);
                    acc0 += wj[j] * f0.x;
                    acc1 += wj[j] * f0.y;
                    acc2 += wj[j] * f1.x;
                    acc3 += wj[j] * f1.y;
                }
            }
            __syncwarp();
        }
    }

    #pragma unroll
    for (int o = 16; o > 0; o >>= 1) {
        sw0 += __shfl_xor_sync(0xffffffffu, sw0, o);
        sw1 += __shfl_xor_sync(0xffffffffu, sw1, o);
        sw2 += __shfl_xor_sync(0xffffffffu, sw2, o);
        sw3 += __shfl_xor_sync(0xffffffffu, sw3, o);
    }
    float denom = (hd == 0) ? sw0 : (hd == 1) ? sw1 : (hd == 2) ? sw2 : sw3;
    float inv = 1.f / denom;
    float4 b4 = *(const float4*)(bias + lane * 4);
    float4 o4;
    o4.x = fmaxf(acc0 * inv + b4.x, 0.f);
    o4.y = fmaxf(acc1 * inv + b4.y, 0.f);
    o4.z = fmaxf(acc2 * inv + b4.z, 0.f);
    o4.w = fmaxf(acc3 * inv + b4.w, 0.f);
    *(float4*)(g_h + n * 128 + lane * 4) = o4;
}

// ---------------- pooling ----------------
__global__ void k_pool_init() {
    int i = blockIdx.x * blockDim.x + threadIdx.x;
    if (i < BG * HID) { g_pool_sum[i] = 0.f; g_pool_max[i] = NEG_INF; }
    if (i < BG) g_cnt[i] = 0.f;
}
__global__ void k_pool(const int* __restrict__ batch) {
    const int NPB = 128;
    int c = threadIdx.x;
    int n0 = blockIdx.x * NPB;
    int n1 = min(n0 + NPB, NN);
    float sum = 0.f, mx = NEG_INF;
    int curb = batch[n0];
    int runlen = 0;
    for (int n = n0; n < n1; n++) {
        int b = batch[n];
        if (b != curb) {
            atomicAdd(&g_pool_sum[curb * HID + c], sum);
            atomicMaxF(&g_pool_max[curb * HID + c], mx);
            if (c == 0) atomicAdd(&g_cnt[curb], (float)runlen);
            sum = 0.f; mx = NEG_INF; runlen = 0; curb = b;
        }
        float v = g_h[n * HID + c];
        sum += v; mx = fmaxf(mx, v); runlen++;
    }
    atomicAdd(&g_pool_sum[curb * HID + c], sum);
    atomicMaxF(&g_pool_max[curb * HID + c], mx);
    if (c == 0) atomicAdd(&g_cnt[curb], (float)runlen);
}

// ---------------- fused head ----------------
__device__ __forceinline__ float blk_reduce_sum320(float v, float* sc) {
    int lane = threadIdx.x & 31, wid = threadIdx.x >> 5;
    #pragma unroll
    for (int o = 16; o > 0; o >>= 1) v += __shfl_xor_sync(0xffffffffu, v, o);
    if (lane == 0) sc[wid] = v;
    __syncthreads();
    float r = 0.f;
    if (wid == 0) {
        r = (lane < 10) ? sc[lane] : 0.f;
        #pragma unroll
        for (int o = 16; o > 0; o >>= 1) r += __shfl_xor_sync(0xffffffffu, r, o);
        if (lane == 0) sc[0] = r;
    }
    __syncthreads();
    r = sc[0];
    __syncthreads();
    return r;
}
__global__ void k_head(float* __restrict__ out, const float* __restrict__ ts,
                       const float* __restrict__ tw1, const float* __restrict__ tb1,
                       const float* __restrict__ tg,  const float* __restrict__ tbln,
                       const float* __restrict__ tw2, const float* __restrict__ tb2,
                       const float* __restrict__ cg,  const float* __restrict__ cbln,
                       const float* __restrict__ cw1, const float* __restrict__ cb1,
                       const float* __restrict__ cw2, const float* __restrict__ cb2) {
    int b = blockIdx.x, t = threadIdx.x;
    int lane = t & 31;
    __shared__ float z[POOLDIM];
    __shared__ float y[HID];
    __shared__ float sc[16];
    __shared__ float tsh[64];
    __shared__ float tws[2];

    float t1 = 0.f;
    bool is_ts = (t >= 256);
    int j = t - 256;
    if (is_ts)
        t1 = tb1[j] + ts[b * 3 + 0] * tw1[j] + ts[b * 3 + 1] * tw1[64 + j]
                    + ts[b * 3 + 2] * tw1[128 + j];
    float r = is_ts ? t1 : 0.f;
    #pragma unroll
    for (int o = 16; o > 0; o >>= 1) r += __shfl_xor_sync(0xffffffffu, r, o);
    if (is_ts && lane == 0) tws[j >> 5] = r;
    __syncthreads();
    float mean64 = (tws[0] + tws[1]) * (1.f / 64.f);
    __syncthreads();
    float dd = is_ts ? (t1 - mean64) : 0.f;
    r = dd * dd;
    #pragma unroll
    for (int o = 16; o > 0; o >>= 1) r += __shfl_xor_sync(0xffffffffu, r, o);
    if (is_ts && lane == 0) tws[j >> 5] = r;
    __syncthreads();
    float var64 = (tws[0] + tws[1]) * (1.f / 64.f);
    if (is_ts)
        tsh[j] = fmaxf(dd * rsqrtf(var64 + 1e-5f) * tg[j] + tbln[j], 0.f);
    __syncthreads();

    float v;
    if (is_ts) {
        float o2 = tb2[j];
        #pragma unroll 8
        for (int k = 0; k < 64; k++) o2 += tsh[k] * tw2[k * 64 + j];
        v = o2;
    } else if (t < 128) {
        v = g_pool_sum[b * HID + t] / fmaxf(g_cnt[b], 1.f);
    } else {
        v = g_pool_max[b * HID + (t - 128)];
    }

    float mean = blk_reduce_sum320(v, sc) * (1.f / (float)POOLDIM);
    float d = v - mean;
    float var = blk_reduce_sum320(d * d, sc) * (1.f / (float)POOLDIM);
    z[t] = d * rsqrtf(var + 1e-5f) * cg[t] + cbln[t];
    __syncthreads();

    if (t < HID) {
        float a = cb1[t];
        #pragma unroll 8
        for (int k = 0; k < POOLDIM; k++) a += z[k] * cw1[k * HID + t];
        y[t] = fmaxf(a, 0.f);
    }
    __syncthreads();
    if (t < NCLS) {
        float a = cb2[t];
        #pragma unroll 8
        for (int k = 0; k < HID; k++) a += y[k] * cw2[k * NCLS + t];
        out[b * NCLS + t] = a;
    }
}

// ---------------- launch ----------------
extern "C" void kernel_launch(void* const* d_in, const int* in_sizes, int n_in,
                              void* d_out, int out_size) {
    const float* x      = (const float*)d_in[0];
    const int*   ei     = (const int*)  d_in[1];
    const int*   batch  = (const int*)  d_in[2];
    const float* ts     = (const float*)d_in[3];
    const float* enc_w  = (const float*)d_in[4];
    const float* enc_b  = (const float*)d_in[5];
    const float* gat_w  = (const float*)d_in[6];
    const float* gat_as = (const float*)d_in[7];
    const float* gat_ad = (const float*)d_in[8];
    const float* gat_b  = (const float*)d_in[9];
    const float* ts_w1  = (const float*)d_in[10];
    const float* ts_b1  = (const float*)d_in[11];
    const float* ts_g   = (const float*)d_in[12];
    const float* ts_bln = (const float*)d_in[13];
    const float* ts_w2  = (const float*)d_in[14];
    const float* ts_b2  = (const float*)d_in[15];
    const float* cls_g  = (const float*)d_in[16];
    const float* cls_bln= (const float*)d_in[17];
    const float* cls_w1 = (const float*)d_in[18];
    const float* cls_b1 = (const float*)d_in[19];
    const float* cls_w2 = (const float*)d_in[20];
    const float* cls_b2 = (const float*)d_in[21];
    float* out = (float*)d_out;

    const int GEMM_SMEM = 131072;
    static bool init_done = false;
    static bool have_s2 = false;
    static cudaStream_t s2 = nullptr;
    static cudaEvent_t evF = nullptr, evJ = nullptr;
    if (!init_done) {
        cudaFuncSetAttribute(k_gemm2, cudaFuncAttributeMaxDynamicSharedMemorySize, GEMM_SMEM);
        if (cudaStreamCreateWithFlags(&s2, cudaStreamNonBlocking) == cudaSuccess &&
            cudaEventCreateWithFlags(&evF, cudaEventDisableTiming) == cudaSuccess &&
            cudaEventCreateWithFlags(&evJ, cudaEventDisableTiming) == cudaSuccess) {
            have_s2 = true;
        }
        init_done = true;
    }

    cudaStream_t sc = have_s2 ? s2 : (cudaStream_t)0;

    // fork: CSR build on side stream (or serial on stream 0 if fork unavailable)
    if (have_s2) {
        cudaEventRecord(evF, 0);
        cudaStreamWaitEvent(s2, evF, 0);
    }
    k_zero_deg<<<(NN + 255) / 256, 256, 0, sc>>>();
    k_count  <<<(ETOT + 255) / 256, 256, 0, sc>>>(ei);
    k_scan1  <<<NBLK, 1024, 0, sc>>>();
    k_scan2  <<<1, 64, 0, sc>>>();
    k_scan3  <<<(NN + 255) / 256, 256, 0, sc>>>();
    k_scatter<<<(ETOT + 255) / 256, 256, 0, sc>>>(ei);
    k_pool_init<<<(BG * HID + 255) / 256, 256, 0, sc>>>();
    if (have_s2) cudaEventRecord(evJ, s2);

    // main stream: layer-0 GEMM with fused encoder (runs concurrent with CSR build)
    k_gemm2<<<(NN + 127) / 128, 256, GEMM_SMEM>>>(
        gat_w, gat_as, gat_ad, x, enc_w, enc_b, 1);

    if (have_s2) cudaStreamWaitEvent(0, evJ, 0);

    k_agg<<<(NN + 7) / 8, 256>>>(gat_b);
    for (int l = 1; l < 3; l++) {
        k_gemm2<<<(NN + 127) / 128, 256, GEMM_SMEM>>>(
            gat_w + l * HID * HID,
            gat_as + l * HEADS * CH, gat_ad + l * HEADS * CH,
            nullptr, nullptr, nullptr, 0);
        k_agg<<<(NN + 7) / 8, 256>>>(gat_b + l * HID);
    }

    k_pool<<<(NN + 127) / 128, 128>>>(batch);
    k_head<<<BG, POOLDIM>>>(out, ts,
                            ts_w1, ts_b1, ts_g, ts_bln, ts_w2, ts_b2,
                            cls_g, cls_bln, cls_w1, cls_b1, cls_w2, cls_b2);
}

// round 16
// speedup vs baseline: 1.0100x; 1.0018x over previous
#include <cuda_runtime.h>
#include <cuda_fp16.h>
#include <cuda_bf16.h>
#include <cstdint>

#define NN      50000
#define EDGES   800000
#define ETOT    850000   // + self loops
#define BG      64
#define HID     128
#define HEADS   4
#define CH      32
#define NCLS    8
#define TSH     64
#define POOLDIM 320
#define L_LAYERS 3
#define NBLK    ((NN + 1023) / 1024)

#define NEG_INF (__int_as_float(0xff800000))

#if defined(__CUDA_ARCH_FEAT_SM103_ALL) || (defined(__CUDA_ARCH__) && defined(__CUDA_ARCH_SPECIFIC__))
#define HAS_F32X2 1
#else
#define HAS_F32X2 0
#endif

// ---------------- device scratch ----------------
__device__ float  g_h   [NN * HID];
__device__ __half g_hh_h[NN * HID];
__device__ float  g_as  [NN * HEADS];
__device__ float  g_ad  [NN * HEADS];
__device__ int    g_deg [NN];
__device__ int    g_cur [NN];
__device__ int    g_off [NN + 1];
__device__ int    g_bsum[NBLK];
__device__ int    g_csr_src[ETOT];
__device__ float  g_pool_sum[BG * HID];
__device__ float  g_pool_max[BG * HID];
__device__ float  g_cnt[BG];

__device__ __forceinline__ void atomicMaxF(float* addr, float v) {
    if (v >= 0.f) atomicMax((int*)addr, __float_as_int(v));
    else          atomicMin((unsigned int*)addr, __float_as_uint(v));
}

// ---------------- CSR build ----------------
__global__ void k_zero_deg() {
    int i = blockIdx.x * blockDim.x + threadIdx.x;
    if (i < NN) g_deg[i] = 0;
}
__global__ void k_count(const int* __restrict__ ei) {
    int e = blockIdx.x * blockDim.x + threadIdx.x;
    if (e >= ETOT) return;
    int dst = (e < EDGES) ? ei[EDGES + e] : (e - EDGES);
    atomicAdd(&g_deg[dst], 1);
}
__global__ void k_scan1() {
    __shared__ int wsum[32];
    int b = blockIdx.x, tid = threadIdx.x, lane = tid & 31, wid = tid >> 5;
    int i = b * 1024 + tid;
    int v = (i < NN) ? g_deg[i] : 0;
    int x = v;
    #pragma unroll
    for (int o = 1; o < 32; o <<= 1) {
        int y = __shfl_up_sync(0xffffffffu, x, o);
        if (lane >= o) x += y;
    }
    if (lane == 31) wsum[wid] = x;
    __syncthreads();
    if (wid == 0) {
        int s = wsum[lane];
        int t = s;
        #pragma unroll
        for (int o = 1; o < 32; o <<= 1) {
            int y = __shfl_up_sync(0xffffffffu, t, o);
            if (lane >= o) t += y;
        }
        wsum[lane] = t - s;
    }
    __syncthreads();
    int incl = x + wsum[wid];
    if (i < NN) g_off[i] = incl - v;
    if (tid == 1023) g_bsum[b] = incl;
}
__global__ void k_scan2() {
    __shared__ int sh[64];
    int tid = threadIdx.x;
    int v = (tid < NBLK) ? g_bsum[tid] : 0;
    sh[tid] = v;
    __syncthreads();
    #pragma unroll
    for (int o = 1; o < 64; o <<= 1) {
        int t = (tid >= o) ? sh[tid - o] : 0;
        __syncthreads();
        sh[tid] += t;
        __syncthreads();
    }
    if (tid < NBLK) g_bsum[tid] = sh[tid] - v;
    if (tid == NBLK - 1) g_off[NN] = sh[tid];
}
__global__ void k_scan3() {
    int i = blockIdx.x * blockDim.x + threadIdx.x;
    if (i < NN) {
        int e = g_off[i] + g_bsum[i >> 10];
        g_off[i] = e;
        g_cur[i] = e;
    }
}
__global__ void k_scatter(const int* __restrict__ ei) {
    int e = blockIdx.x * blockDim.x + threadIdx.x;
    if (e >= ETOT) return;
    int src = (e < EDGES) ? ei[e]         : (e - EDGES);
    int dst = (e < EDGES) ? ei[EDGES + e] : (e - EDGES);
    int pos = atomicAdd(&g_cur[dst], 1);
    g_csr_src[pos] = src;
}

// ---------------- GEMM (f32x2) + fused attn coeffs; hh stored as fp16 ----------------
__global__ __launch_bounds__(256, 1) void k_gemm2(
        const float* __restrict__ Wl,
        const float* __restrict__ as_l, const float* __restrict__ ad_l,
        const float* __restrict__ x, const float* __restrict__ enc_w,
        const float* __restrict__ enc_b, int enc_mode) {
    extern __shared__ float smf[];
    float* sAt = smf;           // [128][128] k-major: sAt[k*128 + r]
    float* sW  = smf + 16384;   // [128][128] k-major: sW [k*128 + c]
    __shared__ float s_as[HID];
    __shared__ float s_ad[HID];
    __shared__ float s_ew[4 * HID + HID];
    int tid = threadIdx.x;
    int row0 = blockIdx.x * 128;

    if (tid < HID) { s_as[tid] = as_l[tid]; s_ad[tid] = ad_l[tid]; }

    for (int i = tid; i < 4096; i += 256)
        ((float4*)sW)[i] = ((const float4*)Wl)[i];

    if (enc_mode) {
        if (tid < 160) ((float4*)s_ew)[tid] = ((const float4*)enc_w)[tid];
        __syncthreads();
        for (int i = tid; i < 4096; i += 256) {
            int r = i & 127, q = i >> 7;
            int gr = row0 + r;
            float4 xr = (gr < NN) ? *(const float4*)(x + gr * 4)
                                  : make_float4(0.f, 0.f, 0.f, 0.f);
            #pragma unroll
            for (int j = 0; j < 4; j++) {
                int k = q * 4 + j;
                float a = s_ew[512 + k]
                        + xr.x * s_ew[k] + xr.y * s_ew[128 + k]
                        + xr.z * s_ew[256 + k] + xr.w * s_ew[384 + k];
                sAt[k * 128 + r] = (gr < NN) ? fmaxf(a, 0.f) : 0.f;
            }
        }
    } else {
        for (int i = tid; i < 4096; i += 256) {
            int r = i & 127, q = i >> 7;
            int gr = row0 + r;
            float4 v = (gr < NN) ? *(const float4*)(g_h + gr * 128 + q * 4)
                                 : make_float4(0.f, 0.f, 0.f, 0.f);
            sAt[(q * 4 + 0) * 128 + r] = v.x;
            sAt[(q * 4 + 1) * 128 + r] = v.y;
            sAt[(q * 4 + 2) * 128 + r] = v.z;
            sAt[(q * 4 + 3) * 128 + r] = v.w;
        }
    }
    __syncthreads();

    int ty = tid >> 4, tx = tid & 15;

#if HAS_F32X2
    unsigned long long acc[8][4];
    #pragma unroll
    for (int i = 0; i < 8; i++)
        #pragma unroll
        for (int j = 0; j < 4; j++) acc[i][j] = 0ull;

    #pragma unroll 2
    for (int k = 0; k < 128; k++) {
        const float* ak = sAt + k * 128 + ty * 8;
        float4 a0 = *(const float4*)ak;
        float4 a1 = *(const float4*)(ak + 4);
        const float* wk = sW + k * 128 + tx * 8;
        float4 w0 = *(const float4*)wk;
        float4 w1 = *(const float4*)(wk + 4);
        unsigned long long wp[4];
        asm("mov.b64 %0, {%1, %2};" : "=l"(wp[0]) : "f"(w0.x), "f"(w0.y));
        asm("mov.b64 %0, {%1, %2};" : "=l"(wp[1]) : "f"(w0.z), "f"(w0.w));
        asm("mov.b64 %0, {%1, %2};" : "=l"(wp[2]) : "f"(w1.x), "f"(w1.y));
        asm("mov.b64 %0, {%1, %2};" : "=l"(wp[3]) : "f"(w1.z), "f"(w1.w));
        float av[8] = {a0.x, a0.y, a0.z, a0.w, a1.x, a1.y, a1.z, a1.w};
        #pragma unroll
        for (int i = 0; i < 8; i++) {
            unsigned long long a2;
            asm("mov.b64 %0, {%1, %1};" : "=l"(a2) : "f"(av[i]));
            #pragma unroll
            for (int j = 0; j < 4; j++)
                asm("fma.rn.f32x2 %0, %1, %2, %0;"
                    : "+l"(acc[i][j]) : "l"(a2), "l"(wp[j]));
        }
    }

    #pragma unroll
    for (int i = 0; i < 8; i++) {
        int row = row0 + ty * 8 + i;
        float c[8];
        #pragma unroll
        for (int j = 0; j < 4; j++)
            asm("mov.b64 {%0, %1}, %2;" : "=f"(c[2*j]), "=f"(c[2*j+1]) : "l"(acc[i][j]));
        float ps = 0.f, pd = 0.f;
        #pragma unroll
        for (int j = 0; j < 8; j++) {
            ps += c[j] * s_as[tx * 8 + j];
            pd += c[j] * s_ad[tx * 8 + j];
        }
        ps += __shfl_xor_sync(0xffffffffu, ps, 1, 4);
        ps += __shfl_xor_sync(0xffffffffu, ps, 2, 4);
        pd += __shfl_xor_sync(0xffffffffu, pd, 1, 4);
        pd += __shfl_xor_sync(0xffffffffu, pd, 2, 4);
        if (row < NN) {
            __half hb[8];
            #pragma unroll
            for (int j = 0; j < 8; j++) hb[j] = __float2half_rn(c[j]);
            *(uint4*)(g_hh_h + row * 128 + tx * 8) = *(const uint4*)hb;
            if ((tx & 3) == 0) {
                g_as[row * 4 + (tx >> 2)] = ps;
                g_ad[row * 4 + (tx >> 2)] = pd;
            }
        }
    }
#else
    float acc[8][8];
    #pragma unroll
    for (int i = 0; i < 8; i++)
        #pragma unroll
        for (int j = 0; j < 8; j++) acc[i][j] = 0.f;

    #pragma unroll 2
    for (int k = 0; k < 128; k++) {
        const float* ak = sAt + k * 128 + ty * 8;
        float4 a0 = *(const float4*)ak;
        float4 a1 = *(const float4*)(ak + 4);
        const float* wk = sW + k * 128 + tx * 8;
        float4 w0 = *(const float4*)wk;
        float4 w1 = *(const float4*)(wk + 4);
        float av[8] = {a0.x, a0.y, a0.z, a0.w, a1.x, a1.y, a1.z, a1.w};
        float wv[8] = {w0.x, w0.y, w0.z, w0.w, w1.x, w1.y, w1.z, w1.w};
        #pragma unroll
        for (int i = 0; i < 8; i++)
            #pragma unroll
            for (int j = 0; j < 8; j++) acc[i][j] += av[i] * wv[j];
    }

    #pragma unroll
    for (int i = 0; i < 8; i++) {
        int row = row0 + ty * 8 + i;
        float ps = 0.f, pd = 0.f;
        #pragma unroll
        for (int j = 0; j < 8; j++) {
            ps += acc[i][j] * s_as[tx * 8 + j];
            pd += acc[i][j] * s_ad[tx * 8 + j];
        }
        ps += __shfl_xor_sync(0xffffffffu, ps, 1, 4);
        ps += __shfl_xor_sync(0xffffffffu, ps, 2, 4);
        pd += __shfl_xor_sync(0xffffffffu, pd, 1, 4);
        pd += __shfl_xor_sync(0xffffffffu, pd, 2, 4);
        if (row < NN) {
            __half hb[8];
            #pragma unroll
            for (int j = 0; j < 8; j++) hb[j] = __float2half_rn(acc[i][j]);
            *(uint4*)(g_hh_h + row * 128 + tx * 8) = *(const uint4*)hb;
            if ((tx & 3) == 0) {
                g_as[row * 4 + (tx >> 2)] = ps;
                g_ad[row * 4 + (tx >> 2)] = pd;
            }
        }
    }
#endif
}

// ---------------- GAT aggregation: warp/node (frozen R8 shape), no-max softmax ----------------
__global__ void k_agg(const float* __restrict__ bias) {
    int w = threadIdx.x >> 5, lane = threadIdx.x & 31;
    int n = blockIdx.x * 8 + w;
    __shared__ int   s_src[8][32];
    __shared__ float s_wv[8][128];
    if (n >= NN) return;

    int beg = g_off[n], end = g_off[n + 1];
    int deg = end - beg;
    float4 ad4 = *(const float4*)(g_ad + n * 4);
    int hd = lane >> 3;
    const __half* hhp = g_hh_h + lane * 4;

    float acc0 = 0.f, acc1 = 0.f, acc2 = 0.f, acc3 = 0.f;
    float sw0 = 0.f, sw1 = 0.f, sw2 = 0.f, sw3 = 0.f;

    if (deg <= 32) {
        int i = beg + lane;
        bool ok = i < end;
        int sidx = ok ? g_csr_src[i] : 0;
        float w0 = 0.f, w1 = 0.f, w2 = 0.f, w3 = 0.f;
        if (ok) {
            float4 a4 = *(const float4*)(g_as + sidx * 4);
            float v;
            v = a4.x + ad4.x; v = v > 0.f ? v : 0.2f * v; w0 = __expf(v);
            v = a4.y + ad4.y; v = v > 0.f ? v : 0.2f * v; w1 = __expf(v);
            v = a4.z + ad4.z; v = v > 0.f ? v : 0.2f * v; w2 = __expf(v);
            v = a4.w + ad4.w; v = v > 0.f ? v : 0.2f * v; w3 = __expf(v);
        }
        sw0 = w0; sw1 = w1; sw2 = w2; sw3 = w3;
        s_src[w][lane] = sidx;
        *(float4*)&s_wv[w][lane * 4] = make_float4(w0, w1, w2, w3);
        __syncwarp();

        int nbp = (deg + 3) & ~3;
        for (int j0 = 0; j0 < nbp; j0 += 4) {
            int srcs[4]; float wj[4]; uint2 u[4];
            #pragma unroll
            for (int j = 0; j < 4; j++) srcs[j] = s_src[w][j0 + j];
            #pragma unroll
            for (int j = 0; j < 4; j++) wj[j] = s_wv[w][(j0 + j) * 4 + hd];
            #pragma unroll
            for (int j = 0; j < 4; j++) u[j] = *(const uint2*)(hhp + srcs[j] * 128);
            #pragma unroll
            for (int j = 0; j < 4; j++) {
                float2 f0 = __half22float2(*(const __half2*)&u[j].x);
                float2 f1 = __half22float2(*(const __half2*)&u[j].y);
                acc0 += wj[j] * f0.x;
                acc1 += wj[j] * f0.y;
                acc2 += wj[j] * f1.x;
                acc3 += wj[j] * f1.y;
            }
        }
    } else {
        for (int base = beg; base < end; base += 32) {
            int i = base + lane;
            float w0 = 0.f, w1 = 0.f, w2 = 0.f, w3 = 0.f;
            int sidx = 0;
            if (i < end) {
                sidx = g_csr_src[i];
                float4 a4 = *(const float4*)(g_as + sidx * 4);
                float v;
                v = a4.x + ad4.x; v = v > 0.f ? v : 0.2f * v; w0 = __expf(v);
                v = a4.y + ad4.y; v = v > 0.f ? v : 0.2f * v; w1 = __expf(v);
                v = a4.z + ad4.z; v = v > 0.f ? v : 0.2f * v; w2 = __expf(v);
                v = a4.w + ad4.w; v = v > 0.f ? v : 0.2f * v; w3 = __expf(v);
            }
            sw0 += w0; sw1 += w1; sw2 += w2; sw3 += w3;
            s_src[w][lane] = sidx;
            *(float4*)&s_wv[w][lane * 4] = make_float4(w0, w1, w2, w3);
            __syncwarp();
            int nb = min(32, end - base);
            int nbp = (nb + 3) & ~3;
            for (int j0 = 0; j0 < nbp; j0 += 4) {
                int srcs[4]; float wj[4]; uint2 u[4];
                #pragma unroll
                for (int j = 0; j < 4; j++) srcs[j] = s_src[w][j0 + j];
                #pragma unroll
                for (int j = 0; j < 4; j++) wj[j] = s_wv[w][(j0 + j) * 4 + hd];
                #pragma unroll
                for (int j = 0; j < 4; j++) u[j] = *(const uint2*)(hhp + srcs[j] * 128);
                #pragma unroll
                for (int j = 0; j < 4; j++) {
                    float2 f0 = __half22float2(*(const __half2*)&u[j].x);
                    float2 f1 = __half22float2(*(const __half2*)&u[j].y);
                    acc0 += wj[j] * f0.x;
                    acc1 += wj[j] * f0.y;
                    acc2 += wj[j] * f1.x;
                    acc3 += wj[j] * f1.y;
                }
            }
            __syncwarp();
        }
    }

    #pragma unroll
    for (int o = 16; o > 0; o >>= 1) {
        sw0 += __shfl_xor_sync(0xffffffffu, sw0, o);
        sw1 += __shfl_xor_sync(0xffffffffu, sw1, o);
        sw2 += __shfl_xor_sync(0xffffffffu, sw2, o);
        sw3 += __shfl_xor_sync(0xffffffffu, sw3, o);
    }
    float denom = (hd == 0) ? sw0 : (hd == 1) ? sw1 : (hd == 2) ? sw2 : sw3;
    float inv = 1.f / denom;
    float4 b4 = *(const float4*)(bias + lane * 4);
    float4 o4;
    o4.x = fmaxf(acc0 * inv + b4.x, 0.f);
    o4.y = fmaxf(acc1 * inv + b4.y, 0.f);
    o4.z = fmaxf(acc2 * inv + b4.z, 0.f);
    o4.w = fmaxf(acc3 * inv + b4.w, 0.f);
    *(float4*)(g_h + n * 128 + lane * 4) = o4;
}

// ---------------- pooling ----------------
__global__ void k_pool_init() {
    int i = blockIdx.x * blockDim.x + threadIdx.x;
    if (i < BG * HID) { g_pool_sum[i] = 0.f; g_pool_max[i] = NEG_INF; }
    if (i < BG) g_cnt[i] = 0.f;
}
__global__ void k_pool(const int* __restrict__ batch) {
    const int NPB = 128;
    int c = threadIdx.x;
    int n0 = blockIdx.x * NPB;
    int n1 = min(n0 + NPB, NN);
    float sum = 0.f, mx = NEG_INF;
    int curb = batch[n0];
    int runlen = 0;
    for (int n = n0; n < n1; n++) {
        int b = batch[n];
        if (b != curb) {
            atomicAdd(&g_pool_sum[curb * HID + c], sum);
            atomicMaxF(&g_pool_max[curb * HID + c], mx);
            if (c == 0) atomicAdd(&g_cnt[curb], (float)runlen);
            sum = 0.f; mx = NEG_INF; runlen = 0; curb = b;
        }
        float v = g_h[n * HID + c];
        sum += v; mx = fmaxf(mx, v); runlen++;
    }
    atomicAdd(&g_pool_sum[curb * HID + c], sum);
    atomicMaxF(&g_pool_max[curb * HID + c], mx);
    if (c == 0) atomicAdd(&g_cnt[curb], (float)runlen);
}

// ---------------- fused head ----------------
__device__ __forceinline__ float blk_reduce_sum320(float v, float* sc) {
    int lane = threadIdx.x & 31, wid = threadIdx.x >> 5;
    #pragma unroll
    for (int o = 16; o > 0; o >>= 1) v += __shfl_xor_sync(0xffffffffu, v, o);
    if (lane == 0) sc[wid] = v;
    __syncthreads();
    float r = 0.f;
    if (wid == 0) {
        r = (lane < 10) ? sc[lane] : 0.f;
        #pragma unroll
        for (int o = 16; o > 0; o >>= 1) r += __shfl_xor_sync(0xffffffffu, r, o);
        if (lane == 0) sc[0] = r;
    }
    __syncthreads();
    r = sc[0];
    __syncthreads();
    return r;
}
__global__ void k_head(float* __restrict__ out, const float* __restrict__ ts,
                       const float* __restrict__ tw1, const float* __restrict__ tb1,
                       const float* __restrict__ tg,  const float* __restrict__ tbln,
                       const float* __restrict__ tw2, const float* __restrict__ tb2,
                       const float* __restrict__ cg,  const float* __restrict__ cbln,
                       const float* __restrict__ cw1, const float* __restrict__ cb1,
                       const float* __restrict__ cw2, const float* __restrict__ cb2) {
    int b = blockIdx.x, t = threadIdx.x;
    int lane = t & 31;
    __shared__ float z[POOLDIM];
    __shared__ float y[HID];
    __shared__ float sc[16];
    __shared__ float tsh[64];
    __shared__ float tws[2];

    float t1 = 0.f;
    bool is_ts = (t >= 256);
    int j = t - 256;
    if (is_ts)
        t1 = tb1[j] + ts[b * 3 + 0] * tw1[j] + ts[b * 3 + 1] * tw1[64 + j]
                    + ts[b * 3 + 2] * tw1[128 + j];
    float r = is_ts ? t1 : 0.f;
    #pragma unroll
    for (int o = 16; o > 0; o >>= 1) r += __shfl_xor_sync(0xffffffffu, r, o);
    if (is_ts && lane == 0) tws[j >> 5] = r;
    __syncthreads();
    float mean64 = (tws[0] + tws[1]) * (1.f / 64.f);
    __syncthreads();
    float dd = is_ts ? (t1 - mean64) : 0.f;
    r = dd * dd;
    #pragma unroll
    for (int o = 16; o > 0; o >>= 1) r += __shfl_xor_sync(0xffffffffu, r, o);
    if (is_ts && lane == 0) tws[j >> 5] = r;
    __syncthreads();
    float var64 = (tws[0] + tws[1]) * (1.f / 64.f);
    if (is_ts)
        tsh[j] = fmaxf(dd * rsqrtf(var64 + 1e-5f) * tg[j] + tbln[j], 0.f);
    __syncthreads();

    float v;
    if (is_ts) {
        float o2 = tb2[j];
        #pragma unroll 8
        for (int k = 0; k < 64; k++) o2 += tsh[k] * tw2[k * 64 + j];
        v = o2;
    } else if (t < 128) {
        v = g_pool_sum[b * HID + t] / fmaxf(g_cnt[b], 1.f);
    } else {
        v = g_pool_max[b * HID + (t - 128)];
    }

    float mean = blk_reduce_sum320(v, sc) * (1.f / (float)POOLDIM);
    float d = v - mean;
    float var = blk_reduce_sum320(d * d, sc) * (1.f / (float)POOLDIM);
    z[t] = d * rsqrtf(var + 1e-5f) * cg[t] + cbln[t];
    __syncthreads();

    if (t < HID) {
        float a = cb1[t];
        #pragma unroll 8
        for (int k = 0; k < POOLDIM; k++) a += z[k] * cw1[k * HID + t];
        y[t] = fmaxf(a, 0.f);
    }
    __syncthreads();
    if (t < NCLS) {
        float a = cb2[t];
        #pragma unroll 8
        for (int k = 0; k < HID; k++) a += y[k] * cw2[k * NCLS + t];
        out[b * NCLS + t] = a;
    }
}

// ---------------- launch ----------------
extern "C" void kernel_launch(void* const* d_in, const int* in_sizes, int n_in,
                              void* d_out, int out_size) {
    const float* x      = (const float*)d_in[0];
    const int*   ei     = (const int*)  d_in[1];
    const int*   batch  = (const int*)  d_in[2];
    const float* ts     = (const float*)d_in[3];
    const float* enc_w  = (const float*)d_in[4];
    const float* enc_b  = (const float*)d_in[5];
    const float* gat_w  = (const float*)d_in[6];
    const float* gat_as = (const float*)d_in[7];
    const float* gat_ad = (const float*)d_in[8];
    const float* gat_b  = (const float*)d_in[9];
    const float* ts_w1  = (const float*)d_in[10];
    const float* ts_b1  = (const float*)d_in[11];
    const float* ts_g   = (const float*)d_in[12];
    const float* ts_bln = (const float*)d_in[13];
    const float* ts_w2  = (const float*)d_in[14];
    const float* ts_b2  = (const float*)d_in[15];
    const float* cls_g  = (const float*)d_in[16];
    const float* cls_bln= (const float*)d_in[17];
    const float* cls_w1 = (const float*)d_in[18];
    const float* cls_b1 = (const float*)d_in[19];
    const float* cls_w2 = (const float*)d_in[20];
    const float* cls_b2 = (const float*)d_in[21];
    float* out = (float*)d_out;

    const int GEMM_SMEM = 131072;
    static bool init_done = false;
    static bool have_s2 = false;
    static cudaStream_t s2 = nullptr;
    static cudaEvent_t evF = nullptr, evJ = nullptr;
    if (!init_done) {
        cudaFuncSetAttribute(k_gemm2, cudaFuncAttributeMaxDynamicSharedMemorySize, GEMM_SMEM);
        if (cudaStreamCreateWithFlags(&s2, cudaStreamNonBlocking) == cudaSuccess &&
            cudaEventCreateWithFlags(&evF, cudaEventDisableTiming) == cudaSuccess &&
            cudaEventCreateWithFlags(&evJ, cudaEventDisableTiming) == cudaSuccess) {
            have_s2 = true;
        }
        init_done = true;
    }

    cudaStream_t sc = have_s2 ? s2 : (cudaStream_t)0;

    // fork: CSR build on side stream (or serial on stream 0 if fork unavailable)
    if (have_s2) {
        cudaEventRecord(evF, 0);
        cudaStreamWaitEvent(s2, evF, 0);
    }
    k_zero_deg<<<(NN + 255) / 256, 256, 0, sc>>>();
    k_count  <<<(ETOT + 255) / 256, 256, 0, sc>>>(ei);
    k_scan1  <<<NBLK, 1024, 0, sc>>>();
    k_scan2  <<<1, 64, 0, sc>>>();
    k_scan3  <<<(NN + 255) / 256, 256, 0, sc>>>();
    k_scatter<<<(ETOT + 255) / 256, 256, 0, sc>>>(ei);
    k_pool_init<<<(BG * HID + 255) / 256, 256, 0, sc>>>();
    if (have_s2) cudaEventRecord(evJ, s2);

    // main stream: layer-0 GEMM with fused encoder (runs concurrent with CSR build)
    k_gemm2<<<(NN + 127) / 128, 256, GEMM_SMEM>>>(
        gat_w, gat_as, gat_ad, x, enc_w, enc_b, 1);

    if (have_s2) cudaStreamWaitEvent(0, evJ, 0);

    k_agg<<<(NN + 7) / 8, 256>>>(gat_b);
    for (int l = 1; l < 3; l++) {
        k_gemm2<<<(NN + 127) / 128, 256, GEMM_SMEM>>>(
            gat_w + l * HID * HID,
            gat_as + l * HEADS * CH, gat_ad + l * HEADS * CH,
            nullptr, nullptr, nullptr, 0);
        k_agg<<<(NN + 7) / 8, 256>>>(gat_b + l * HID);
    }

    k_pool<<<(NN + 127) / 128, 128>>>(batch);
    k_head<<<BG, POOLDIM>>>(out, ts,
                            ts_w1, ts_b1, ts_g, ts_bln, ts_w2, ts_b2,
                            cls_g, cls_bln, cls_w1, cls_b1, cls_w2, cls_b2);
}